// round 9
// baseline (speedup 1.0000x reference)
#include <cuda_runtime.h>
#include <cuda_fp16.h>
#include <math.h>

// Problem constants (fixed dataset)
#define NN   50000
#define EE   800000
#define ETOT 850000     // edges + self loops
#define HCC  256        // heads*hid
#define NEG  0.2f
#define BNEPS 1e-5f

// ---------------- scratch (device globals; no allocation allowed) ----------------
__device__ __align__(16) float   g_h[NN * HCC];      // current node features
__device__ __align__(16) float   g_hprev[NN * HCC];  // residual save
__device__ __align__(16) __half2 g_xlh[NN * 128];    // xl in fp16 (256 half / node)
__device__ __align__(16) float   g_xr[NN * HCC];     // xr in fp32
__device__ __align__(16) float   g_o2l[2 * NN];      // output-layer xl (C=2)
__device__ __align__(16) float   g_o2r[2 * NN];      // output-layer xr (C=2)
__device__ int g_deg[NN];
__device__ int g_rowptr[NN + 1];
__device__ int g_cur[NN];
__device__ int g_esrc[ETOT];                         // src ids grouped by dst (CSR)

// ---------------- helpers ----------------
__device__ __forceinline__ float lrelu(float v) { return v > 0.f ? v : NEG * v; }

// ---------------- CSR build ----------------
__global__ void hist_dst(const int* __restrict__ ei)
{
    int e = blockIdx.x * blockDim.x + threadIdx.x;
    if (e >= ETOT) return;
    int d = (e < EE) ? ei[EE + e] : (e - EE);
    atomicAdd(&g_deg[d], 1);
}

// single-block exclusive scan over g_deg -> g_rowptr / g_cur
__global__ void scan_deg()
{
    __shared__ int sh[1024];
    __shared__ int carry;
    int tid = threadIdx.x;
    if (tid == 0) carry = 0;
    __syncthreads();
    for (int base = 0; base < NN; base += 1024) {
        int i = base + tid;
        int v = (i < NN) ? g_deg[i] : 0;
        sh[tid] = v;
        __syncthreads();
        for (int off = 1; off < 1024; off <<= 1) {
            int t = 0;
            if (tid >= off) t = sh[tid - off];
            __syncthreads();
            if (tid >= off) sh[tid] += t;
            __syncthreads();
        }
        int excl = sh[tid] - v;
        if (i < NN) { g_rowptr[i] = carry + excl; g_cur[i] = carry + excl; }
        __syncthreads();
        if (tid == 1023) carry += sh[1023];
        __syncthreads();
    }
    if (tid == 0) g_rowptr[NN] = ETOT;
}

__global__ void scatter_src(const int* __restrict__ ei)
{
    int e = blockIdx.x * blockDim.x + threadIdx.x;
    if (e >= ETOT) return;
    int s, d;
    if (e < EE) { s = ei[e]; d = ei[EE + e]; } else { s = e - EE; d = s; }
    int pos = atomicAdd(&g_cur[d], 1);
    g_esrc[pos] = s;
}

// ---------------- tiled SGEMM: BM=128, BN=64, BK=16, 256 thr, 8x4/thread ----------------
// blockIdx.z==0: act(A@W1) -> Ch (half2) if Ch!=nullptr else Cf.  z==1: A@W2 -> Cf2.
// Nc multiple of 64, K multiple of 16.
__global__ void gemm128(const float* __restrict__ A, const float* __restrict__ W1,
                        const float* __restrict__ W2,
                        const float* __restrict__ bias,
                        float* __restrict__ Cf, __half2* __restrict__ Ch,
                        float* __restrict__ Cf2,
                        int M, int K, int Nc, int do_relu)
{
    __shared__ float As[16][128];
    __shared__ float Ws[16][64];
    const float* W = (blockIdx.z == 0) ? W1 : W2;
    const int bm0 = blockIdx.x * 128;
    const int n0  = blockIdx.y * 64;
    const int tid = threadIdx.x;
    const int ty = tid >> 4, tx = tid & 15;

    float acc[8][4] = {};

    for (int k0 = 0; k0 < K; k0 += 16) {
        // A tile [128 x 16]: each thread loads 8 k-values of one row
        {
            int m = tid >> 1, kh = (tid & 1) * 8;
            float4 av0 = make_float4(0.f, 0.f, 0.f, 0.f);
            float4 av1 = make_float4(0.f, 0.f, 0.f, 0.f);
            if (bm0 + m < M) {
                const float* ap = A + (size_t)(bm0 + m) * K + k0 + kh;
                av0 = *reinterpret_cast<const float4*>(ap);
                av1 = *reinterpret_cast<const float4*>(ap + 4);
            }
            As[kh + 0][m] = av0.x; As[kh + 1][m] = av0.y;
            As[kh + 2][m] = av0.z; As[kh + 3][m] = av0.w;
            As[kh + 4][m] = av1.x; As[kh + 5][m] = av1.y;
            As[kh + 6][m] = av1.z; As[kh + 7][m] = av1.w;
        }
        // W tile [16 x 64]
        {
            int kk = tid >> 4, nq = tid & 15;
            float4 wv = *reinterpret_cast<const float4*>(W + (size_t)(k0 + kk) * Nc + n0 + nq * 4);
            *reinterpret_cast<float4*>(&Ws[kk][nq * 4]) = wv;
        }
        __syncthreads();
#pragma unroll
        for (int k = 0; k < 16; k++) {
            float4 a0 = *reinterpret_cast<const float4*>(&As[k][ty * 8]);
            float4 a1 = *reinterpret_cast<const float4*>(&As[k][ty * 8 + 4]);
            float4 b  = *reinterpret_cast<const float4*>(&Ws[k][tx * 4]);
            float av[8] = {a0.x, a0.y, a0.z, a0.w, a1.x, a1.y, a1.z, a1.w};
#pragma unroll
            for (int i = 0; i < 8; i++) {
                acc[i][0] += av[i] * b.x;
                acc[i][1] += av[i] * b.y;
                acc[i][2] += av[i] * b.z;
                acc[i][3] += av[i] * b.w;
            }
        }
        __syncthreads();
    }

    const int colb = n0 + tx * 4;
#pragma unroll
    for (int i = 0; i < 8; i++) {
        int row = bm0 + ty * 8 + i;
        if (row >= M) continue;
        float v0 = acc[i][0], v1 = acc[i][1], v2 = acc[i][2], v3 = acc[i][3];
        if (bias) { v0 += bias[colb]; v1 += bias[colb + 1]; v2 += bias[colb + 2]; v3 += bias[colb + 3]; }
        if (do_relu) { v0 = fmaxf(v0, 0.f); v1 = fmaxf(v1, 0.f); v2 = fmaxf(v2, 0.f); v3 = fmaxf(v3, 0.f); }
        if (blockIdx.z == 0) {
            if (Ch) {
                __half2* hp = Ch + ((size_t)row * Nc + colb) / 2;
                hp[0] = __floats2half2_rn(v0, v1);
                hp[1] = __floats2half2_rn(v2, v3);
            } else {
                float* cp = Cf + (size_t)row * Nc + colb;
                cp[0] = v0; cp[1] = v1; cp[2] = v2; cp[3] = v3;
            }
        } else {
            float* cp = Cf2 + (size_t)row * Nc + colb;
            cp[0] = v0; cp[1] = v1; cp[2] = v2; cp[3] = v3;
        }
    }
}

// ---------------- CSR gather-aggregation (4 heads, C=64) + fused epilogue ----------------
// One warp per destination node. lane covers channels [lane*8, lane*8+8); head = lane>>3.
// xl gathered as fp16 (16B/lane/edge), all math fp32.
__global__ void agg4_csr(const float* __restrict__ att, const float* __restrict__ bias,
                         const float* __restrict__ gamma, const float* __restrict__ beta,
                         const float* __restrict__ mean, const float* __restrict__ var,
                         int add_residual, int save_prev)
{
    int n = (blockIdx.x * blockDim.x + threadIdx.x) >> 5;
    if (n >= NN) return;
    int lane = threadIdx.x & 31;

    const float4* xr = reinterpret_cast<const float4*>(&g_xr[(size_t)n * 256 + lane * 8]);
    float4 r0 = xr[0], r1 = xr[1];
    const float4* at = reinterpret_cast<const float4*>(&att[lane * 8]);
    float4 t0 = at[0], t1 = at[1];

    float4 acc0 = make_float4(0.f, 0.f, 0.f, 0.f);
    float4 acc1 = make_float4(0.f, 0.f, 0.f, 0.f);
    float den = 0.f;

    int i0 = g_rowptr[n], i1 = g_rowptr[n + 1];
#pragma unroll 2
    for (int i = i0; i < i1; i++) {
        int s = g_esrc[i];
        uint4 u = *reinterpret_cast<const uint4*>(&g_xlh[(size_t)s * 128 + lane * 4]);
        float2 f0 = __half22float2(*reinterpret_cast<const __half2*>(&u.x));
        float2 f1 = __half22float2(*reinterpret_cast<const __half2*>(&u.y));
        float2 f2 = __half22float2(*reinterpret_cast<const __half2*>(&u.z));
        float2 f3 = __half22float2(*reinterpret_cast<const __half2*>(&u.w));

        float p = t0.x * lrelu(f0.x + r0.x) + t0.y * lrelu(f0.y + r0.y)
                + t0.z * lrelu(f1.x + r0.z) + t0.w * lrelu(f1.y + r0.w)
                + t1.x * lrelu(f2.x + r1.x) + t1.y * lrelu(f2.y + r1.y)
                + t1.z * lrelu(f3.x + r1.z) + t1.w * lrelu(f3.y + r1.w);
        p += __shfl_xor_sync(0xffffffffu, p, 1);
        p += __shfl_xor_sync(0xffffffffu, p, 2);
        p += __shfl_xor_sync(0xffffffffu, p, 4);

        float ex = __expf(p);
        den += ex;
        acc0.x += ex * f0.x; acc0.y += ex * f0.y; acc0.z += ex * f1.x; acc0.w += ex * f1.y;
        acc1.x += ex * f2.x; acc1.y += ex * f2.y; acc1.z += ex * f3.x; acc1.w += ex * f3.y;
    }

    float inv = 1.f / den;
    int c = lane * 8;
    float4 bi0 = *reinterpret_cast<const float4*>(&bias[c]);
    float4 bi1 = *reinterpret_cast<const float4*>(&bias[c + 4]);
    float4 gm0 = *reinterpret_cast<const float4*>(&gamma[c]);
    float4 gm1 = *reinterpret_cast<const float4*>(&gamma[c + 4]);
    float4 be0 = *reinterpret_cast<const float4*>(&beta[c]);
    float4 be1 = *reinterpret_cast<const float4*>(&beta[c + 4]);
    float4 mn0 = *reinterpret_cast<const float4*>(&mean[c]);
    float4 mn1 = *reinterpret_cast<const float4*>(&mean[c + 4]);
    float4 va0 = *reinterpret_cast<const float4*>(&var[c]);
    float4 va1 = *reinterpret_cast<const float4*>(&var[c + 4]);

    float4 v0, v1;
    v0.x = fmaxf(gm0.x * (acc0.x * inv + bi0.x - mn0.x) * rsqrtf(va0.x + BNEPS) + be0.x, 0.f);
    v0.y = fmaxf(gm0.y * (acc0.y * inv + bi0.y - mn0.y) * rsqrtf(va0.y + BNEPS) + be0.y, 0.f);
    v0.z = fmaxf(gm0.z * (acc0.z * inv + bi0.z - mn0.z) * rsqrtf(va0.z + BNEPS) + be0.z, 0.f);
    v0.w = fmaxf(gm0.w * (acc0.w * inv + bi0.w - mn0.w) * rsqrtf(va0.w + BNEPS) + be0.w, 0.f);
    v1.x = fmaxf(gm1.x * (acc1.x * inv + bi1.x - mn1.x) * rsqrtf(va1.x + BNEPS) + be1.x, 0.f);
    v1.y = fmaxf(gm1.y * (acc1.y * inv + bi1.y - mn1.y) * rsqrtf(va1.y + BNEPS) + be1.y, 0.f);
    v1.z = fmaxf(gm1.z * (acc1.z * inv + bi1.z - mn1.z) * rsqrtf(va1.z + BNEPS) + be1.z, 0.f);
    v1.w = fmaxf(gm1.w * (acc1.w * inv + bi1.w - mn1.w) * rsqrtf(va1.w + BNEPS) + be1.w, 0.f);

    float* hp = &g_hprev[(size_t)n * 256 + c];
    if (add_residual) {
        float4 p0 = *reinterpret_cast<const float4*>(hp);
        float4 p1 = *reinterpret_cast<const float4*>(hp + 4);
        v0.x += p0.x; v0.y += p0.y; v0.z += p0.z; v0.w += p0.w;
        v1.x += p1.x; v1.y += p1.y; v1.z += p1.z; v1.w += p1.w;
    }
    if (save_prev) {
        *reinterpret_cast<float4*>(hp)     = v0;
        *reinterpret_cast<float4*>(hp + 4) = v1;
    }
    float* ho = &g_h[(size_t)n * 256 + c];
    *reinterpret_cast<float4*>(ho)     = v0;
    *reinterpret_cast<float4*>(ho + 4) = v1;
}

// ---------------- layer 2: tiny GEMM (256 -> 2, both Wl and Wr), warp per row ----------------
__global__ void gemm_out2(const float* __restrict__ Wl, const float* __restrict__ Wr)
{
    int w = (blockIdx.x * blockDim.x + threadIdx.x) >> 5;
    if (w >= NN) return;
    int lane = threadIdx.x & 31;
    const float* hr = &g_h[(size_t)w * 256];
    float s0 = 0.f, s1 = 0.f, t0 = 0.f, t1 = 0.f;
    for (int k = lane; k < 256; k += 32) {
        float a = hr[k];
        s0 += a * Wl[2 * k];     s1 += a * Wl[2 * k + 1];
        t0 += a * Wr[2 * k];     t1 += a * Wr[2 * k + 1];
    }
#pragma unroll
    for (int o = 16; o; o >>= 1) {
        s0 += __shfl_xor_sync(0xffffffffu, s0, o);
        s1 += __shfl_xor_sync(0xffffffffu, s1, o);
        t0 += __shfl_xor_sync(0xffffffffu, t0, o);
        t1 += __shfl_xor_sync(0xffffffffu, t1, o);
    }
    if (lane == 0) {
        g_o2l[2 * w] = s0;   g_o2l[2 * w + 1] = s1;
        g_o2r[2 * w] = t0;   g_o2r[2 * w + 1] = t1;
    }
}

// ---------------- output layer CSR aggregation (1 head, C=2) + log_softmax ----------------
__global__ void agg2_csr(const float* __restrict__ att, const float* __restrict__ bias,
                         float* __restrict__ out)
{
    int n = (blockIdx.x * blockDim.x + threadIdx.x) >> 5;
    if (n >= NN) return;
    int lane = threadIdx.x & 31;

    float b0 = g_o2r[2 * n], b1 = g_o2r[2 * n + 1];
    float at0 = att[0], at1 = att[1];

    float den = 0.f, s0 = 0.f, s1 = 0.f;
    int i0 = g_rowptr[n], i1 = g_rowptr[n + 1];
    for (int i = i0 + lane; i < i1; i += 32) {
        int s = g_esrc[i];
        float a0 = g_o2l[2 * s], a1 = g_o2l[2 * s + 1];
        float l = at0 * lrelu(a0 + b0) + at1 * lrelu(a1 + b1);
        float ex = __expf(l);
        den += ex; s0 += ex * a0; s1 += ex * a1;
    }
#pragma unroll
    for (int o = 16; o; o >>= 1) {
        den += __shfl_xor_sync(0xffffffffu, den, o);
        s0  += __shfl_xor_sync(0xffffffffu, s0, o);
        s1  += __shfl_xor_sync(0xffffffffu, s1, o);
    }
    if (lane == 0) {
        float inv = 1.f / den;
        float o0 = s0 * inv + bias[0];
        float o1 = s1 * inv + bias[1];
        float mx = fmaxf(o0, o1);
        float lse = mx + logf(expf(o0 - mx) + expf(o1 - mx));
        out[2 * n]     = o0 - lse;
        out[2 * n + 1] = o1 - lse;
    }
}

// ---------------- launch ----------------
extern "C" void kernel_launch(void* const* d_in, const int* in_sizes, int n_in,
                              void* d_out, int out_size)
{
    const float* x      = (const float*)d_in[0];
    const int*   ei     = (const int*)  d_in[1];
    const float* W_in   = (const float*)d_in[2];
    const float* b_in   = (const float*)d_in[3];
    const float* Wl0    = (const float*)d_in[4];
    const float* Wr0    = (const float*)d_in[5];
    const float* att0   = (const float*)d_in[6];
    const float* bias0  = (const float*)d_in[7];
    const float* Wl1    = (const float*)d_in[8];
    const float* Wr1    = (const float*)d_in[9];
    const float* att1   = (const float*)d_in[10];
    const float* bias1  = (const float*)d_in[11];
    const float* Wl2    = (const float*)d_in[12];
    const float* Wr2    = (const float*)d_in[13];
    const float* att2   = (const float*)d_in[14];
    const float* bias2  = (const float*)d_in[15];
    const float* bn_g   = (const float*)d_in[16];
    const float* bn_b   = (const float*)d_in[17];
    const float* bn_m   = (const float*)d_in[18];
    const float* bn_v   = (const float*)d_in[19];
    float* out = (float*)d_out;

    void* tmp;
    cudaGetSymbolAddress(&tmp, g_h);    float*   hA   = (float*)tmp;
    cudaGetSymbolAddress(&tmp, g_xlh);  __half2* xlhA = (__half2*)tmp;
    cudaGetSymbolAddress(&tmp, g_xr);   float*   xrA  = (float*)tmp;
    cudaGetSymbolAddress(&tmp, g_deg);  int*     degA = (int*)tmp;

    const int MBLK = (NN + 127) / 128;               // 391
    const int EDGE_THR_BLKS = (ETOT + 255) / 256;
    const int NODE_WARP_BLKS = (NN * 32 + 255) / 256;  // 6250

    // ---- CSR build (dst-grouped src list), reused by all 3 layers ----
    cudaMemsetAsync(degA, 0, (size_t)NN * sizeof(int));
    hist_dst<<<EDGE_THR_BLKS, 256>>>(ei);
    scan_deg<<<1, 1024>>>();
    scatter_src<<<EDGE_THR_BLKS, 256>>>(ei);

    // input projection: h = relu(x @ W_in + b_in)   [N,64] (fp32 out)
    gemm128<<<dim3(MBLK, 1, 1), 256>>>(x, W_in, nullptr, b_in, hA, nullptr, nullptr,
                                       NN, 128, 64, 1);

    // ---- GAT layer 0: xl (half) + xr (fp32) fused over z ----
    gemm128<<<dim3(MBLK, 4, 2), 256>>>(hA, Wl0, Wr0, nullptr, nullptr, xlhA, xrA,
                                       NN, 64, 256, 0);
    agg4_csr<<<NODE_WARP_BLKS, 256>>>(att0, bias0, bn_g, bn_b, bn_m, bn_v, 0, 1);

    // ---- GAT layer 1 (residual) ----
    gemm128<<<dim3(MBLK, 4, 2), 256>>>(hA, Wl1, Wr1, nullptr, nullptr, xlhA, xrA,
                                       NN, 256, 256, 0);
    agg4_csr<<<NODE_WARP_BLKS, 256>>>(att1, bias1, bn_g + 256, bn_b + 256, bn_m + 256, bn_v + 256, 1, 0);

    // ---- output GAT layer (1 head, C=2) ----
    gemm_out2<<<NODE_WARP_BLKS, 256>>>(Wl2, Wr2);
    agg2_csr<<<NODE_WARP_BLKS, 256>>>(att2, bias2, out);
}

// round 11
// speedup vs baseline: 1.4200x; 1.4200x over previous
#include <cuda_runtime.h>
#include <cuda_fp16.h>
#include <math.h>

// Problem constants (fixed dataset)
#define NN   50000
#define EE   800000
#define ETOT 850000     // edges + self loops
#define HCC  256        // heads*hid
#define NEG  0.2f
#define BNEPS 1e-5f

// ---------------- scratch (device globals; no allocation allowed) ----------------
__device__ __align__(16) float   g_h[NN * HCC];      // current node features
__device__ __align__(16) float   g_hprev[NN * HCC];  // residual save
__device__ __align__(16) __half2 g_xlh[NN * 128];    // xl in fp16 (256 half / node)
__device__ __align__(16) float   g_xr[NN * HCC];     // xr in fp32
__device__ __align__(16) float   g_o2l[2 * NN];      // output-layer xl (C=2)
__device__ __align__(16) float   g_o2r[2 * NN];      // output-layer xr (C=2)
__device__ int g_deg[NN];
__device__ int g_rowptr[NN + 1];
__device__ int g_cur[NN];
__device__ int g_esrc[ETOT];                         // src ids grouped by dst (CSR)

// ---------------- helpers ----------------
__device__ __forceinline__ float lrelu(float v) { return v > 0.f ? v : NEG * v; }

// ---------------- CSR build ----------------
__global__ void hist_dst(const int* __restrict__ ei)
{
    int e = blockIdx.x * blockDim.x + threadIdx.x;
    if (e >= ETOT) return;
    int d = (e < EE) ? ei[EE + e] : (e - EE);
    atomicAdd(&g_deg[d], 1);
}

// single-block exclusive scan over g_deg -> g_rowptr / g_cur
__global__ void scan_deg()
{
    __shared__ int sh[1024];
    __shared__ int carry;
    int tid = threadIdx.x;
    if (tid == 0) carry = 0;
    __syncthreads();
    for (int base = 0; base < NN; base += 1024) {
        int i = base + tid;
        int v = (i < NN) ? g_deg[i] : 0;
        sh[tid] = v;
        __syncthreads();
        for (int off = 1; off < 1024; off <<= 1) {
            int t = 0;
            if (tid >= off) t = sh[tid - off];
            __syncthreads();
            if (tid >= off) sh[tid] += t;
            __syncthreads();
        }
        int excl = sh[tid] - v;
        if (i < NN) { g_rowptr[i] = carry + excl; g_cur[i] = carry + excl; }
        __syncthreads();
        if (tid == 1023) carry += sh[1023];
        __syncthreads();
    }
    if (tid == 0) g_rowptr[NN] = ETOT;
}

__global__ void scatter_src(const int* __restrict__ ei)
{
    int e = blockIdx.x * blockDim.x + threadIdx.x;
    if (e >= ETOT) return;
    int s, d;
    if (e < EE) { s = ei[e]; d = ei[EE + e]; } else { s = e - EE; d = s; }
    int pos = atomicAdd(&g_cur[d], 1);
    g_esrc[pos] = s;
}

// ---------------- tiled SGEMM (R7-proven shape): BM=BN=64, BK=16, 256 thr, 4x4/thread ----
// blockIdx.z==0: act(A@W1) -> Ch (half2) if Ch!=nullptr else Cf.  z==1: A@W2 -> Cf2 (fp32).
// Nc multiple of 64, K multiple of 16.
__global__ void gemm64(const float* __restrict__ A, const float* __restrict__ W1,
                       const float* __restrict__ W2,
                       const float* __restrict__ bias,
                       float* __restrict__ Cf, __half2* __restrict__ Ch,
                       float* __restrict__ Cf2,
                       int M, int K, int Nc, int do_relu)
{
    __shared__ float As[16][64];
    __shared__ float Ws[16][64];
    const float* W = (blockIdx.z == 0) ? W1 : W2;
    const int bm0 = blockIdx.x * 64;
    const int n0  = blockIdx.y * 64;
    const int tid = threadIdx.x;
    const int ty = tid >> 4, tx = tid & 15;

    float acc[4][4] = {};

    for (int k0 = 0; k0 < K; k0 += 16) {
        {
            int m = tid >> 2, kq = tid & 3;
            float4 av = make_float4(0.f, 0.f, 0.f, 0.f);
            if (bm0 + m < M)
                av = *reinterpret_cast<const float4*>(A + (size_t)(bm0 + m) * K + k0 + kq * 4);
            As[kq * 4 + 0][m] = av.x;
            As[kq * 4 + 1][m] = av.y;
            As[kq * 4 + 2][m] = av.z;
            As[kq * 4 + 3][m] = av.w;
        }
        {
            int kk = tid >> 4, nq = tid & 15;
            float4 wv = *reinterpret_cast<const float4*>(W + (size_t)(k0 + kk) * Nc + n0 + nq * 4);
            *reinterpret_cast<float4*>(&Ws[kk][nq * 4]) = wv;
        }
        __syncthreads();
#pragma unroll
        for (int k = 0; k < 16; k++) {
            float4 a = *reinterpret_cast<const float4*>(&As[k][ty * 4]);
            float4 b = *reinterpret_cast<const float4*>(&Ws[k][tx * 4]);
            acc[0][0] += a.x * b.x; acc[0][1] += a.x * b.y; acc[0][2] += a.x * b.z; acc[0][3] += a.x * b.w;
            acc[1][0] += a.y * b.x; acc[1][1] += a.y * b.y; acc[1][2] += a.y * b.z; acc[1][3] += a.y * b.w;
            acc[2][0] += a.z * b.x; acc[2][1] += a.z * b.y; acc[2][2] += a.z * b.z; acc[2][3] += a.z * b.w;
            acc[3][0] += a.w * b.x; acc[3][1] += a.w * b.y; acc[3][2] += a.w * b.z; acc[3][3] += a.w * b.w;
        }
        __syncthreads();
    }

    const int colb = n0 + tx * 4;
#pragma unroll
    for (int i = 0; i < 4; i++) {
        int row = bm0 + ty * 4 + i;
        if (row >= M) continue;
        float v0 = acc[i][0], v1 = acc[i][1], v2 = acc[i][2], v3 = acc[i][3];
        if (bias) { v0 += bias[colb]; v1 += bias[colb + 1]; v2 += bias[colb + 2]; v3 += bias[colb + 3]; }
        if (do_relu) { v0 = fmaxf(v0, 0.f); v1 = fmaxf(v1, 0.f); v2 = fmaxf(v2, 0.f); v3 = fmaxf(v3, 0.f); }
        if (blockIdx.z == 0) {
            if (Ch) {
                __half2* hp = Ch + ((size_t)row * Nc + colb) / 2;
                hp[0] = __floats2half2_rn(v0, v1);
                hp[1] = __floats2half2_rn(v2, v3);
            } else {
                float* cp = Cf + (size_t)row * Nc + colb;
                cp[0] = v0; cp[1] = v1; cp[2] = v2; cp[3] = v3;
            }
        } else {
            float* cp = Cf2 + (size_t)row * Nc + colb;
            cp[0] = v0; cp[1] = v1; cp[2] = v2; cp[3] = v3;
        }
    }
}

// ---------------- CSR gather-aggregation (4 heads, C=64) + fused epilogue ----------------
// One warp per destination node. lane covers channels [lane*8, lane*8+8); head = lane>>3.
// xl gathered as fp16 (one uint4 / lane / edge); esrc index software-pipelined.
__global__ void agg4_csr(const float* __restrict__ att, const float* __restrict__ bias,
                         const float* __restrict__ gamma, const float* __restrict__ beta,
                         const float* __restrict__ mean, const float* __restrict__ var,
                         int add_residual, int save_prev)
{
    int n = (blockIdx.x * blockDim.x + threadIdx.x) >> 5;
    if (n >= NN) return;
    int lane = threadIdx.x & 31;

    const float4* xr = reinterpret_cast<const float4*>(&g_xr[(size_t)n * 256 + lane * 8]);
    float4 r0 = xr[0], r1 = xr[1];
    const float4* at = reinterpret_cast<const float4*>(&att[lane * 8]);
    float4 t0 = at[0], t1 = at[1];

    float4 acc0 = make_float4(0.f, 0.f, 0.f, 0.f);
    float4 acc1 = make_float4(0.f, 0.f, 0.f, 0.f);
    float den = 0.f;

    int i0 = g_rowptr[n], i1 = g_rowptr[n + 1];
    int s = g_esrc[i0];                       // prefetch first index
    for (int i = i0; i < i1; i++) {
        uint4 u = *reinterpret_cast<const uint4*>(&g_xlh[(size_t)s * 128 + lane * 4]);
        if (i + 1 < i1) s = g_esrc[i + 1];    // next index load overlaps this edge's math
        float2 f0 = __half22float2(*reinterpret_cast<const __half2*>(&u.x));
        float2 f1 = __half22float2(*reinterpret_cast<const __half2*>(&u.y));
        float2 f2 = __half22float2(*reinterpret_cast<const __half2*>(&u.z));
        float2 f3 = __half22float2(*reinterpret_cast<const __half2*>(&u.w));

        float p = t0.x * lrelu(f0.x + r0.x) + t0.y * lrelu(f0.y + r0.y)
                + t0.z * lrelu(f1.x + r0.z) + t0.w * lrelu(f1.y + r0.w)
                + t1.x * lrelu(f2.x + r1.x) + t1.y * lrelu(f2.y + r1.y)
                + t1.z * lrelu(f3.x + r1.z) + t1.w * lrelu(f3.y + r1.w);
        p += __shfl_xor_sync(0xffffffffu, p, 1);
        p += __shfl_xor_sync(0xffffffffu, p, 2);
        p += __shfl_xor_sync(0xffffffffu, p, 4);

        float ex = __expf(p);
        den += ex;
        acc0.x += ex * f0.x; acc0.y += ex * f0.y; acc0.z += ex * f1.x; acc0.w += ex * f1.y;
        acc1.x += ex * f2.x; acc1.y += ex * f2.y; acc1.z += ex * f3.x; acc1.w += ex * f3.y;
    }

    float inv = 1.f / den;
    int c = lane * 8;
    float4 bi0 = *reinterpret_cast<const float4*>(&bias[c]);
    float4 bi1 = *reinterpret_cast<const float4*>(&bias[c + 4]);
    float4 gm0 = *reinterpret_cast<const float4*>(&gamma[c]);
    float4 gm1 = *reinterpret_cast<const float4*>(&gamma[c + 4]);
    float4 be0 = *reinterpret_cast<const float4*>(&beta[c]);
    float4 be1 = *reinterpret_cast<const float4*>(&beta[c + 4]);
    float4 mn0 = *reinterpret_cast<const float4*>(&mean[c]);
    float4 mn1 = *reinterpret_cast<const float4*>(&mean[c + 4]);
    float4 va0 = *reinterpret_cast<const float4*>(&var[c]);
    float4 va1 = *reinterpret_cast<const float4*>(&var[c + 4]);

    float4 v0, v1;
    v0.x = fmaxf(gm0.x * (acc0.x * inv + bi0.x - mn0.x) * rsqrtf(va0.x + BNEPS) + be0.x, 0.f);
    v0.y = fmaxf(gm0.y * (acc0.y * inv + bi0.y - mn0.y) * rsqrtf(va0.y + BNEPS) + be0.y, 0.f);
    v0.z = fmaxf(gm0.z * (acc0.z * inv + bi0.z - mn0.z) * rsqrtf(va0.z + BNEPS) + be0.z, 0.f);
    v0.w = fmaxf(gm0.w * (acc0.w * inv + bi0.w - mn0.w) * rsqrtf(va0.w + BNEPS) + be0.w, 0.f);
    v1.x = fmaxf(gm1.x * (acc1.x * inv + bi1.x - mn1.x) * rsqrtf(va1.x + BNEPS) + be1.x, 0.f);
    v1.y = fmaxf(gm1.y * (acc1.y * inv + bi1.y - mn1.y) * rsqrtf(va1.y + BNEPS) + be1.y, 0.f);
    v1.z = fmaxf(gm1.z * (acc1.z * inv + bi1.z - mn1.z) * rsqrtf(va1.z + BNEPS) + be1.z, 0.f);
    v1.w = fmaxf(gm1.w * (acc1.w * inv + bi1.w - mn1.w) * rsqrtf(va1.w + BNEPS) + be1.w, 0.f);

    float* hp = &g_hprev[(size_t)n * 256 + c];
    if (add_residual) {
        float4 p0 = *reinterpret_cast<const float4*>(hp);
        float4 p1 = *reinterpret_cast<const float4*>(hp + 4);
        v0.x += p0.x; v0.y += p0.y; v0.z += p0.z; v0.w += p0.w;
        v1.x += p1.x; v1.y += p1.y; v1.z += p1.z; v1.w += p1.w;
    }
    if (save_prev) {
        *reinterpret_cast<float4*>(hp)     = v0;
        *reinterpret_cast<float4*>(hp + 4) = v1;
    }
    float* ho = &g_h[(size_t)n * 256 + c];
    *reinterpret_cast<float4*>(ho)     = v0;
    *reinterpret_cast<float4*>(ho + 4) = v1;
}

// ---------------- layer 2: tiny GEMM (256 -> 2, both Wl and Wr), warp per row ----------------
__global__ void gemm_out2(const float* __restrict__ Wl, const float* __restrict__ Wr)
{
    int w = (blockIdx.x * blockDim.x + threadIdx.x) >> 5;
    if (w >= NN) return;
    int lane = threadIdx.x & 31;
    const float* hr = &g_h[(size_t)w * 256];
    float s0 = 0.f, s1 = 0.f, t0 = 0.f, t1 = 0.f;
    for (int k = lane; k < 256; k += 32) {
        float a = hr[k];
        s0 += a * Wl[2 * k];     s1 += a * Wl[2 * k + 1];
        t0 += a * Wr[2 * k];     t1 += a * Wr[2 * k + 1];
    }
#pragma unroll
    for (int o = 16; o; o >>= 1) {
        s0 += __shfl_xor_sync(0xffffffffu, s0, o);
        s1 += __shfl_xor_sync(0xffffffffu, s1, o);
        t0 += __shfl_xor_sync(0xffffffffu, t0, o);
        t1 += __shfl_xor_sync(0xffffffffu, t1, o);
    }
    if (lane == 0) {
        g_o2l[2 * w] = s0;   g_o2l[2 * w + 1] = s1;
        g_o2r[2 * w] = t0;   g_o2r[2 * w + 1] = t1;
    }
}

// ---------------- output layer CSR aggregation (1 head, C=2) + log_softmax ----------------
__global__ void agg2_csr(const float* __restrict__ att, const float* __restrict__ bias,
                         float* __restrict__ out)
{
    int n = (blockIdx.x * blockDim.x + threadIdx.x) >> 5;
    if (n >= NN) return;
    int lane = threadIdx.x & 31;

    float b0 = g_o2r[2 * n], b1 = g_o2r[2 * n + 1];
    float at0 = att[0], at1 = att[1];

    float den = 0.f, s0 = 0.f, s1 = 0.f;
    int i0 = g_rowptr[n], i1 = g_rowptr[n + 1];
    for (int i = i0 + lane; i < i1; i += 32) {
        int s = g_esrc[i];
        float a0 = g_o2l[2 * s], a1 = g_o2l[2 * s + 1];
        float l = at0 * lrelu(a0 + b0) + at1 * lrelu(a1 + b1);
        float ex = __expf(l);
        den += ex; s0 += ex * a0; s1 += ex * a1;
    }
#pragma unroll
    for (int o = 16; o; o >>= 1) {
        den += __shfl_xor_sync(0xffffffffu, den, o);
        s0  += __shfl_xor_sync(0xffffffffu, s0, o);
        s1  += __shfl_xor_sync(0xffffffffu, s1, o);
    }
    if (lane == 0) {
        float inv = 1.f / den;
        float o0 = s0 * inv + bias[0];
        float o1 = s1 * inv + bias[1];
        float mx = fmaxf(o0, o1);
        float lse = mx + logf(expf(o0 - mx) + expf(o1 - mx));
        out[2 * n]     = o0 - lse;
        out[2 * n + 1] = o1 - lse;
    }
}

// ---------------- launch ----------------
extern "C" void kernel_launch(void* const* d_in, const int* in_sizes, int n_in,
                              void* d_out, int out_size)
{
    const float* x      = (const float*)d_in[0];
    const int*   ei     = (const int*)  d_in[1];
    const float* W_in   = (const float*)d_in[2];
    const float* b_in   = (const float*)d_in[3];
    const float* Wl0    = (const float*)d_in[4];
    const float* Wr0    = (const float*)d_in[5];
    const float* att0   = (const float*)d_in[6];
    const float* bias0  = (const float*)d_in[7];
    const float* Wl1    = (const float*)d_in[8];
    const float* Wr1    = (const float*)d_in[9];
    const float* att1   = (const float*)d_in[10];
    const float* bias1  = (const float*)d_in[11];
    const float* Wl2    = (const float*)d_in[12];
    const float* Wr2    = (const float*)d_in[13];
    const float* att2   = (const float*)d_in[14];
    const float* bias2  = (const float*)d_in[15];
    const float* bn_g   = (const float*)d_in[16];
    const float* bn_b   = (const float*)d_in[17];
    const float* bn_m   = (const float*)d_in[18];
    const float* bn_v   = (const float*)d_in[19];
    float* out = (float*)d_out;

    void* tmp;
    cudaGetSymbolAddress(&tmp, g_h);    float*   hA   = (float*)tmp;
    cudaGetSymbolAddress(&tmp, g_xlh);  __half2* xlhA = (__half2*)tmp;
    cudaGetSymbolAddress(&tmp, g_xr);   float*   xrA  = (float*)tmp;
    cudaGetSymbolAddress(&tmp, g_deg);  int*     degA = (int*)tmp;

    const int MBLK = (NN + 63) / 64;                 // 782
    const int EDGE_THR_BLKS = (ETOT + 255) / 256;
    const int NODE_WARP_BLKS = (NN * 32 + 255) / 256;  // 6250

    // ---- CSR build (dst-grouped src list), reused by all 3 layers ----
    cudaMemsetAsync(degA, 0, (size_t)NN * sizeof(int));
    hist_dst<<<EDGE_THR_BLKS, 256>>>(ei);
    scan_deg<<<1, 1024>>>();
    scatter_src<<<EDGE_THR_BLKS, 256>>>(ei);

    // input projection: h = relu(x @ W_in + b_in)   [N,64] (fp32 out)
    gemm64<<<dim3(MBLK, 1, 1), 256>>>(x, W_in, nullptr, b_in, hA, nullptr, nullptr,
                                      NN, 128, 64, 1);

    // ---- GAT layer 0: xl (half) + xr (fp32) fused over z ----
    gemm64<<<dim3(MBLK, 4, 2), 256>>>(hA, Wl0, Wr0, nullptr, nullptr, xlhA, xrA,
                                      NN, 64, 256, 0);
    agg4_csr<<<NODE_WARP_BLKS, 256>>>(att0, bias0, bn_g, bn_b, bn_m, bn_v, 0, 1);

    // ---- GAT layer 1 (residual) ----
    gemm64<<<dim3(MBLK, 4, 2), 256>>>(hA, Wl1, Wr1, nullptr, nullptr, xlhA, xrA,
                                      NN, 256, 256, 0);
    agg4_csr<<<NODE_WARP_BLKS, 256>>>(att1, bias1, bn_g + 256, bn_b + 256, bn_m + 256, bn_v + 256, 1, 0);

    // ---- output GAT layer (1 head, C=2) ----
    gemm_out2<<<NODE_WARP_BLKS, 256>>>(Wl2, Wr2);
    agg2_csr<<<NODE_WARP_BLKS, 256>>>(att2, bias2, out);
}